// round 3
// baseline (speedup 1.0000x reference)
#include <cuda_runtime.h>
#include <cuda_bf16.h>

// PowerSpectrum: out[n, l*512 + q*16 + p] = cg[l] * sum_m x_nu[l,n,m,q] * x_1[l,n,m,p]
// L=4, M=7, F_NU=32, F_1=16.
//
// Round-3: streaming cache hints (__ldcs/__stcs) on all touch-once global
// traffic, and 2 samples per 256-thread CTA (warp w handles (n + (w>>2), l=w&3)).
// Store mapping unchanged from round 2: lane j owns p-quad (j&3)*4 and
// q = (j>>2)+8k, giving exactly contiguous 512B per warp STG.

#define PS_L  4
#define PS_M  7
#define PS_FN 32
#define PS_FP 16
#define OUT_PER_N (PS_L * PS_FN * PS_FP)     // 2048
#define XNU_PER_LN (PS_M * PS_FN)            // 224 floats (56 float4)
#define X1_PER_LN  (PS_M * PS_FP)            // 112 floats (28 float4)
#define NB 2                                  // samples per CTA

__global__ __launch_bounds__(128 * NB)
void ps_kernel(const float* __restrict__ x_nu,
               const float* __restrict__ x_1,
               float* __restrict__ out,
               int N)
{
    __shared__ float xns[NB * PS_L * XNU_PER_LN];   // 2*896 floats
    __shared__ float x1s[NB * PS_L * X1_PER_LN];    // 2*448 floats

    const int n0 = blockIdx.x * NB;
    const int t  = threadIdx.x;

    // ---- Cooperative load of both tiles for NB samples (672 float4 total) ----
    // xns layout: [s][l][m*32+q]; x1s layout: [s][l][m*16+p]
#pragma unroll
    for (int f = t; f < NB * 336; f += 128 * NB) {
        const int s = f / 336;          // sample slot
        const int g = f % 336;
        if (g < 224) {
            const int l   = g / 56;
            const int idx = g % 56;
            const float4* src = reinterpret_cast<const float4*>(x_nu) +
                                ((size_t)l * N + n0 + s) * 56 + idx;
            reinterpret_cast<float4*>(xns)[(s * PS_L + l) * 56 + idx] = __ldcs(src);
        } else {
            const int h   = g - 224;
            const int l   = h / 28;
            const int idx = h % 28;
            const float4* src = reinterpret_cast<const float4*>(x_1) +
                                ((size_t)l * N + n0 + s) * 28 + idx;
            reinterpret_cast<float4*>(x1s)[(s * PS_L + l) * 28 + idx] = __ldcs(src);
        }
    }
    __syncthreads();

    const int w  = t >> 5;      // warp 0..7
    const int s  = w >> 2;      // sample slot 0..1
    const int l  = w & 3;       // angular channel
    const int j  = t & 31;      // lane
    const int qb = j >> 2;      // q base 0..7 (q = qb + 8k)
    const int pq = j & 3;       // p-quad index (p = pq*4 .. pq*4+3)

    const float*  an = xns + (s * PS_L + l) * XNU_PER_LN;
    const float4* bp = reinterpret_cast<const float4*>(x1s) + (s * PS_L + l) * 28 + pq;

    float4 acc0 = make_float4(0.f, 0.f, 0.f, 0.f);
    float4 acc1 = acc0, acc2 = acc0, acc3 = acc0;

#pragma unroll
    for (int m = 0; m < PS_M; m++) {
        const float4 b = bp[m * 4];
        const float a0 = an[m * PS_FN + qb +  0];
        const float a1 = an[m * PS_FN + qb +  8];
        const float a2 = an[m * PS_FN + qb + 16];
        const float a3 = an[m * PS_FN + qb + 24];

        acc0.x = fmaf(a0, b.x, acc0.x);
        acc0.y = fmaf(a0, b.y, acc0.y);
        acc0.z = fmaf(a0, b.z, acc0.z);
        acc0.w = fmaf(a0, b.w, acc0.w);
        acc1.x = fmaf(a1, b.x, acc1.x);
        acc1.y = fmaf(a1, b.y, acc1.y);
        acc1.z = fmaf(a1, b.z, acc1.z);
        acc1.w = fmaf(a1, b.w, acc1.w);
        acc2.x = fmaf(a2, b.x, acc2.x);
        acc2.y = fmaf(a2, b.y, acc2.y);
        acc2.z = fmaf(a2, b.z, acc2.z);
        acc2.w = fmaf(a2, b.w, acc2.w);
        acc3.x = fmaf(a3, b.x, acc3.x);
        acc3.y = fmaf(a3, b.y, acc3.y);
        acc3.z = fmaf(a3, b.z, acc3.z);
        acc3.w = fmaf(a3, b.w, acc3.w);
    }

    const float cgs[PS_L] = {1.0f, 0.57735026918962576f,
                             0.44721359549995794f, 0.37796447300922722f};
    const float cg = cgs[l];

    acc0.x *= cg; acc0.y *= cg; acc0.z *= cg; acc0.w *= cg;
    acc1.x *= cg; acc1.y *= cg; acc1.z *= cg; acc1.w *= cg;
    acc2.x *= cg; acc2.y *= cg; acc2.z *= cg; acc2.w *= cg;
    acc3.x *= cg; acc3.y *= cg; acc3.z *= cg; acc3.w *= cg;

    // float4 output index within (n,l) block = j + 32k -> contiguous 512B per STG
    float4* o = reinterpret_cast<float4*>(
        out + (size_t)(n0 + s) * OUT_PER_N + l * (PS_FN * PS_FP));
    __stcs(o + j +  0, acc0);
    __stcs(o + j + 32, acc1);
    __stcs(o + j + 64, acc2);
    __stcs(o + j + 96, acc3);
}

extern "C" void kernel_launch(void* const* d_in, const int* in_sizes, int n_in,
                              void* d_out, int out_size)
{
    const float* x_nu = (const float*)d_in[0];
    const float* x_1  = (const float*)d_in[1];
    float* out = (float*)d_out;

    const int N = in_sizes[0] / (PS_L * PS_M * PS_FN);

    ps_kernel<<<N / NB, 128 * NB>>>(x_nu, x_1, out, N);
}

// round 4
// speedup vs baseline: 1.2564x; 1.2564x over previous
#include <cuda_runtime.h>
#include <cuda_bf16.h>

// PowerSpectrum: out[n, l*512 + q*16 + p] = cg[l] * sum_m x_nu[l,n,m,q] * x_1[l,n,m,p]
// L=4, M=7, F_NU=32, F_1=16.
//
// Round-4: R2 skeleton with WARP-PRIVATE smem staging. Each warp owns one (n, l):
// it loads its own 56 float4 of x_nu and 28 float4 of x_1 (<=3 LDG.128/lane),
// __syncwarp()s, and computes — no CTA-wide barrier, no inter-warp coupling.
// Store mapping unchanged: lane j owns p-quad (j&3)*4 and q=(j>>2)+8k, making
// every warp STG.128 exactly contiguous 512B. 8 warps (2 samples) per CTA.

#define PS_L  4
#define PS_M  7
#define PS_FN 32
#define PS_FP 16
#define OUT_PER_N (PS_L * PS_FN * PS_FP)     // 2048
#define WARPS_PER_CTA 8                      // 2 samples x 4 l-channels
#define F4_PER_WARP 84                       // 56 (x_nu) + 28 (x_1)

__global__ __launch_bounds__(32 * WARPS_PER_CTA)
void ps_kernel(const float* __restrict__ x_nu,
               const float* __restrict__ x_1,
               float* __restrict__ out,
               int N)
{
    // warp-private regions: [warp][84 float4]
    __shared__ float4 sm[WARPS_PER_CTA * F4_PER_WARP];

    const int t = threadIdx.x;
    const int w = t >> 5;                  // warp 0..7
    const int j = t & 31;                  // lane
    const int s = w >> 2;                  // sample slot 0..1
    const int l = w & 3;                   // angular channel
    const int n = blockIdx.x * 2 + s;

    // ---- Warp-private load: 56 float4 x_nu then 28 float4 x_1 ----
    const float4* gx = reinterpret_cast<const float4*>(x_nu) + ((size_t)l * N + n) * 56;
    const float4* g1 = reinterpret_cast<const float4*>(x_1)  + ((size_t)l * N + n) * 28;
    float4* smw = sm + w * F4_PER_WARP;

    // f = j (always x_nu), f = 32+j (x_nu if j<24 else x_1), f = 64+j (x_1, j<20)
    const float4 v0 = gx[j];
    const float4 v1 = (j < 24) ? gx[32 + j] : g1[j - 24];
    float4 v2;
    if (j < 20) v2 = g1[8 + j];

    smw[j]      = v0;
    smw[32 + j] = v1;
    if (j < 20) smw[64 + j] = v2;
    __syncwarp();

    const int qb = j >> 2;                 // q base 0..7 (q = qb + 8k)
    const int pq = j & 3;                  // p-quad (p = pq*4 .. pq*4+3)

    const float*  an = reinterpret_cast<const float*>(smw);        // x_nu: [m*32 + q]
    const float4* bp = smw + 56 + pq;                              // x_1:  [m*4 + pq]

    float4 acc0 = make_float4(0.f, 0.f, 0.f, 0.f);
    float4 acc1 = acc0, acc2 = acc0, acc3 = acc0;

#pragma unroll
    for (int m = 0; m < PS_M; m++) {
        const float4 b = bp[m * 4];
        const float a0 = an[m * PS_FN + qb +  0];
        const float a1 = an[m * PS_FN + qb +  8];
        const float a2 = an[m * PS_FN + qb + 16];
        const float a3 = an[m * PS_FN + qb + 24];

        acc0.x = fmaf(a0, b.x, acc0.x);
        acc0.y = fmaf(a0, b.y, acc0.y);
        acc0.z = fmaf(a0, b.z, acc0.z);
        acc0.w = fmaf(a0, b.w, acc0.w);
        acc1.x = fmaf(a1, b.x, acc1.x);
        acc1.y = fmaf(a1, b.y, acc1.y);
        acc1.z = fmaf(a1, b.z, acc1.z);
        acc1.w = fmaf(a1, b.w, acc1.w);
        acc2.x = fmaf(a2, b.x, acc2.x);
        acc2.y = fmaf(a2, b.y, acc2.y);
        acc2.z = fmaf(a2, b.z, acc2.z);
        acc2.w = fmaf(a2, b.w, acc2.w);
        acc3.x = fmaf(a3, b.x, acc3.x);
        acc3.y = fmaf(a3, b.y, acc3.y);
        acc3.z = fmaf(a3, b.z, acc3.z);
        acc3.w = fmaf(a3, b.w, acc3.w);
    }

    const float cgs[PS_L] = {1.0f, 0.57735026918962576f,
                             0.44721359549995794f, 0.37796447300922722f};
    const float cg = cgs[l];

    acc0.x *= cg; acc0.y *= cg; acc0.z *= cg; acc0.w *= cg;
    acc1.x *= cg; acc1.y *= cg; acc1.z *= cg; acc1.w *= cg;
    acc2.x *= cg; acc2.y *= cg; acc2.z *= cg; acc2.w *= cg;
    acc3.x *= cg; acc3.y *= cg; acc3.z *= cg; acc3.w *= cg;

    // float4 index within (n,l) block = j + 32k -> contiguous 512B per STG
    float4* o = reinterpret_cast<float4*>(
        out + (size_t)n * OUT_PER_N + l * (PS_FN * PS_FP));
    o[j +  0] = acc0;
    o[j + 32] = acc1;
    o[j + 64] = acc2;
    o[j + 96] = acc3;
}

extern "C" void kernel_launch(void* const* d_in, const int* in_sizes, int n_in,
                              void* d_out, int out_size)
{
    const float* x_nu = (const float*)d_in[0];
    const float* x_1  = (const float*)d_in[1];
    float* out = (float*)d_out;

    const int N = in_sizes[0] / (PS_L * PS_M * PS_FN);

    ps_kernel<<<N / 2, 32 * WARPS_PER_CTA>>>(x_nu, x_1, out, N);
}